// round 2
// baseline (speedup 1.0000x reference)
#include <cuda_runtime.h>

#define HID     32
#define EDIM    16
#define EH      128
#define TE      128      // edges per CTA
#define KC      16       // W2 rows staged per chunk
#define NTHREADS 256

#define H_STRIDE (EH + 5)    // 133 floats: conflict-free for the he[] access pattern
#define X_STRIDE (HID + 1)   // 33 floats: conflict-free for xi access pattern

struct Smem {
    float h[TE][H_STRIDE];          // relu(ef@W1+b1), per-edge hidden
    float x[TE][X_STRIDE];          // gathered nf[src]
    union {
        float w2[KC * HID * HID];   // 16 x 1024 chunk of W2
        struct {
            float ef[TE][EDIM];
            float w1[EDIM][EH];
            float b1[EH];
        } a;
    } u;
};

__global__ void init_out_kernel(float* __restrict__ out,
                                const float* __restrict__ bias, int n) {
    int i = blockIdx.x * blockDim.x + threadIdx.x;
    if (i < n) out[i] = bias[i & (HID - 1)];
}

__global__ __launch_bounds__(NTHREADS, 1)
void mpnn_edge_kernel(const float* __restrict__ nf,
                      const float* __restrict__ ef,
                      const int*   __restrict__ src,
                      const int*   __restrict__ dst,
                      const float* __restrict__ W1,
                      const float* __restrict__ b1,
                      const float* __restrict__ W2,
                      const float* __restrict__ b2,
                      float* __restrict__ out,
                      int E) {
    extern __shared__ char smem_raw[];
    Smem& s = *reinterpret_cast<Smem*>(smem_raw);
    const int t = threadIdx.x;
    const int e0g = blockIdx.x * TE;

    // ---------------- Phase 0: cooperative loads ----------------
    // ef tile: TE*EDIM = 2048 floats = 512 float4 (guard edge tail)
    {
        const float4* efg = reinterpret_cast<const float4*>(ef);
        float4* efs = reinterpret_cast<float4*>(&s.u.a.ef[0][0]);
        for (int i = t; i < TE * EDIM / 4; i += NTHREADS) {
            int ge = e0g + (i >> 2);  // 4 float4 per edge
            float4 v = make_float4(0.f, 0.f, 0.f, 0.f);
            if (ge < E) v = efg[(size_t)e0g * 4 + i];
            efs[i] = v;
        }
    }
    // W1: 2048 floats, b1: 128 floats
    {
        const float4* w1g = reinterpret_cast<const float4*>(W1);
        float4* w1s = reinterpret_cast<float4*>(&s.u.a.w1[0][0]);
        for (int i = t; i < EDIM * EH / 4; i += NTHREADS) w1s[i] = w1g[i];
        const float4* b1g = reinterpret_cast<const float4*>(b1);
        float4* b1s = reinterpret_cast<float4*>(&s.u.a.b1[0]);
        for (int i = t; i < EH / 4; i += NTHREADS) b1s[i] = b1g[i];
    }
    // x gather: nf[src[e]] rows (8 float4 per edge), zero for tail edges
    {
        const float4* nfg = reinterpret_cast<const float4*>(nf);
        for (int j = t; j < TE * 8; j += NTHREADS) {
            int e = j >> 3;
            int c = j & 7;
            int ge = e0g + e;
            float4 v = make_float4(0.f, 0.f, 0.f, 0.f);
            if (ge < E) {
                int sn = src[ge];
                v = nfg[(size_t)sn * 8 + c];
            }
            s.x[e][c * 4 + 0] = v.x;
            s.x[e][c * 4 + 1] = v.y;
            s.x[e][c * 4 + 2] = v.z;
            s.x[e][c * 4 + 3] = v.w;
        }
    }
    __syncthreads();

    // ---------------- Phase A: h = relu(ef @ W1 + b1) ----------------
    {
        int e  = t >> 1;
        int j0 = (t & 1) * 64;
        float er[EDIM];
#pragma unroll
        for (int d = 0; d < EDIM; d++) er[d] = s.u.a.ef[e][d];
#pragma unroll
        for (int jj = 0; jj < 64; jj += 4) {
            int j = j0 + jj;
            float4 acc = *reinterpret_cast<const float4*>(&s.u.a.b1[j]);
#pragma unroll
            for (int d = 0; d < EDIM; d++) {
                float4 w = *reinterpret_cast<const float4*>(&s.u.a.w1[d][j]);
                acc.x += er[d] * w.x;
                acc.y += er[d] * w.y;
                acc.z += er[d] * w.z;
                acc.w += er[d] * w.w;
            }
            s.h[e][j + 0] = fmaxf(acc.x, 0.f);
            s.h[e][j + 1] = fmaxf(acc.y, 0.f);
            s.h[e][j + 2] = fmaxf(acc.z, 0.f);
            s.h[e][j + 3] = fmaxf(acc.w, 0.f);
        }
    }
    // (barrier folded into first mainloop iteration's leading __syncthreads)

    // ---------------- Main loop: msg = Σ_{k,i} h[k] x[i] W2[k, i*32+o] ----------
    const int e0 = (t >> 3) * 4;   // 32 m-groups x 4 edges
    const int o0 = (t & 7) * 4;    // 8 n-groups x 4 outputs
    float acc[4][4];
#pragma unroll
    for (int m = 0; m < 4; m++)
#pragma unroll
        for (int j = 0; j < 4; j++) acc[m][j] = 0.f;

    for (int kk0 = 0; kk0 < EH; kk0 += KC) {
        __syncthreads();   // previous-chunk consumers done / phase A visible
        {
            const float4* g = reinterpret_cast<const float4*>(W2 + (size_t)kk0 * HID * HID);
            float4* ws = reinterpret_cast<float4*>(&s.u.w2[0]);
#pragma unroll
            for (int i = t; i < KC * HID * HID / 4; i += NTHREADS) ws[i] = g[i];
        }
        __syncthreads();

#pragma unroll
        for (int kkl = 0; kkl < KC; ++kkl) {
            float he[4];
#pragma unroll
            for (int m = 0; m < 4; m++) he[m] = s.h[e0 + m][kk0 + kkl];
            const float* wrow = &s.u.w2[kkl * HID * HID];
#pragma unroll 8
            for (int ii = 0; ii < HID; ++ii) {
                float4 w = *reinterpret_cast<const float4*>(wrow + ii * HID + o0);
#pragma unroll
                for (int m = 0; m < 4; m++) {
                    float p = he[m] * s.x[e0 + m][ii];
                    acc[m][0] += p * w.x;
                    acc[m][1] += p * w.y;
                    acc[m][2] += p * w.z;
                    acc[m][3] += p * w.w;
                }
            }
        }
    }

    // ---------------- Epilogue: + x @ reshape(b2, [32,32]) ----------------
#pragma unroll 8
    for (int ii = 0; ii < HID; ++ii) {
        float4 b = __ldg(reinterpret_cast<const float4*>(b2 + ii * HID + o0));
#pragma unroll
        for (int m = 0; m < 4; m++) {
            float xi = s.x[e0 + m][ii];
            acc[m][0] += xi * b.x;
            acc[m][1] += xi * b.y;
            acc[m][2] += xi * b.z;
            acc[m][3] += xi * b.w;
        }
    }

    // ---------------- Scatter-add to destination nodes ----------------
#pragma unroll
    for (int m = 0; m < 4; m++) {
        int ge = e0g + e0 + m;
        if (ge < E) {
            int d = dst[ge];
            float* op = out + (size_t)d * HID + o0;
            atomicAdd(op + 0, acc[m][0]);
            atomicAdd(op + 1, acc[m][1]);
            atomicAdd(op + 2, acc[m][2]);
            atomicAdd(op + 3, acc[m][3]);
        }
    }
}

extern "C" void kernel_launch(void* const* d_in, const int* in_sizes, int n_in,
                              void* d_out, int out_size) {
    const float* nf   = (const float*)d_in[0];
    const float* ef   = (const float*)d_in[1];
    const int*   src  = (const int*)d_in[2];
    const int*   dst  = (const int*)d_in[3];
    const float* W1   = (const float*)d_in[4];
    const float* b1   = (const float*)d_in[5];
    const float* W2   = (const float*)d_in[6];
    const float* b2   = (const float*)d_in[7];
    const float* bias = (const float*)d_in[8];
    float* out = (float*)d_out;

    const int E = in_sizes[2];
    const int smem_bytes = (int)sizeof(Smem);

    cudaFuncSetAttribute(mpnn_edge_kernel,
                         cudaFuncAttributeMaxDynamicSharedMemorySize, smem_bytes);

    init_out_kernel<<<(out_size + 255) / 256, 256>>>(out, bias, out_size);

    int grid = (E + TE - 1) / TE;
    mpnn_edge_kernel<<<grid, NTHREADS, smem_bytes>>>(
        nf, ef, src, dst, W1, b1, W2, b2, out, E);
}

// round 4
// speedup vs baseline: 3.3386x; 3.3386x over previous
#include <cuda_runtime.h>
#include <cuda_bf16.h>
#include <cstdint>

#define HID   32
#define EDIM  16
#define EH    128
#define TE    128
#define NTH   256
#define H_STRIDE 132
#define X_STRIDE 33

// ---- smem offsets (bytes) ----
#define OFF_X    0          // 128 x 33 f32 = 16896
#define OFF_B2   16896      // 4096
#define OFF_EF   21504      // 8192
#define OFF_W1   29696      // 8192
#define OFF_B1   37888      // 512
#define OFF_R    38912      // 67584 : s_h fp32 [128][132]  (later reused as B buffers)
#define OFF_BB0  OFF_R
#define OFF_BB1  (OFF_R + 32768)
#define SMEM_TOTAL 106496

// W2 pre-split into mma.sync fragment order: [nt(128)][ks(8)][lane(32)] = {hi01,hi23,lo01,lo23}
__device__ uint4 g_Bfrag[128 * 8 * 32];

__device__ __forceinline__ uint32_t smem_u32(const void* p) {
    uint32_t a;
    asm("{ .reg .u64 t; cvta.to.shared.u64 t, %1; cvt.u32.u64 %0, t; }" : "=r"(a) : "l"(p));
    return a;
}
__device__ __forceinline__ uint32_t pkh(__nv_bfloat16 a, __nv_bfloat16 b) {
    __nv_bfloat162 v = __halves2bfloat162(a, b);
    return *reinterpret_cast<uint32_t*>(&v);
}
// split pair of floats into bf16 hi/lo packed regs
__device__ __forceinline__ void split2(float a, float b, uint32_t& hi, uint32_t& lo) {
    __nv_bfloat16 ha = __float2bfloat16(a), hb = __float2bfloat16(b);
    float ra = a - __bfloat162float(ha);
    float rb = b - __bfloat162float(hb);
    hi = pkh(ha, hb);
    lo = pkh(__float2bfloat16(ra), __float2bfloat16(rb));
}
__device__ __forceinline__ void mma_bf16(float& d0, float& d1, float& d2, float& d3,
                                         uint32_t a0, uint32_t a1, uint32_t a2, uint32_t a3,
                                         uint32_t b0, uint32_t b1) {
    asm volatile(
        "mma.sync.aligned.m16n8k16.row.col.f32.bf16.bf16.f32 "
        "{%0,%1,%2,%3}, {%4,%5,%6,%7}, {%8,%9}, {%0,%1,%2,%3};"
        : "+f"(d0), "+f"(d1), "+f"(d2), "+f"(d3)
        : "r"(a0), "r"(a1), "r"(a2), "r"(a3), "r"(b0), "r"(b1));
}

// ---------------- prep: W2 -> fragment-ordered bf16 hi/lo ----------------
__global__ void prep_b_kernel(const float* __restrict__ W2) {
    int idx = blockIdx.x * blockDim.x + threadIdx.x;
    if (idx >= 128 * 8 * 32) return;
    int lane = idx & 31, ks = (idx >> 5) & 7, nt = idx >> 8;
    int g = lane >> 2, c = lane & 3;
    int n = nt * 8 + g;
    int k0 = ks * 16 + 2 * c;
    float v0 = W2[(size_t)k0 * 1024 + n];
    float v1 = W2[(size_t)(k0 + 1) * 1024 + n];
    float v2 = W2[(size_t)(k0 + 8) * 1024 + n];
    float v3 = W2[(size_t)(k0 + 9) * 1024 + n];
    uint4 r;
    split2(v0, v1, r.x, r.z);
    split2(v2, v3, r.y, r.w);
    g_Bfrag[idx] = r;
}

__global__ void init_out_kernel(float* __restrict__ out,
                                const float* __restrict__ bias, int n) {
    int i = blockIdx.x * blockDim.x + threadIdx.x;
    if (i < n) out[i] = bias[i & (HID - 1)];
}

// ---------------- main fused kernel ----------------
__global__ __launch_bounds__(NTH, 1)
void mpnn_mma_kernel(const float* __restrict__ nf,
                     const float* __restrict__ ef,
                     const int*   __restrict__ src,
                     const int*   __restrict__ dst,
                     const float* __restrict__ W1,
                     const float* __restrict__ b1,
                     const float* __restrict__ b2,
                     float* __restrict__ out,
                     int E) {
    extern __shared__ __align__(1024) char sm[];
    const uint32_t sbase = smem_u32(sm);
    const int t = threadIdx.x;
    const int wid = t >> 5;
    const int lane = t & 31;
    const int e0g = blockIdx.x * TE;

    float* s_x  = (float*)(sm + OFF_X);
    float* s_b2 = (float*)(sm + OFF_B2);
    float* s_ef = (float*)(sm + OFF_EF);
    float* s_w1 = (float*)(sm + OFF_W1);
    float* s_b1 = (float*)(sm + OFF_B1);
    float* s_h  = (float*)(sm + OFF_R);

    // -------- phase 0: cooperative loads --------
    {
        const float4* efg = (const float4*)ef;
        float4* efs = (float4*)s_ef;
        for (int i = t; i < TE * EDIM / 4; i += NTH) {
            int ge = e0g + (i >> 2);
            float4 v = make_float4(0.f, 0.f, 0.f, 0.f);
            if (ge < E) v = efg[(size_t)e0g * 4 + i];
            efs[i] = v;
        }
        const float4* w1g = (const float4*)W1;
        float4* w1s = (float4*)s_w1;
        for (int i = t; i < EDIM * EH / 4; i += NTH) w1s[i] = w1g[i];
        if (t < EH / 4) ((float4*)s_b1)[t] = ((const float4*)b1)[t];
        for (int i = t; i < HID * HID / 4; i += NTH)
            ((float4*)s_b2)[i] = ((const float4*)b2)[i];
        const float4* nfg = (const float4*)nf;
        for (int j = t; j < TE * 8; j += NTH) {
            int e = j >> 3, c = j & 7, ge = e0g + e;
            float4 v = make_float4(0.f, 0.f, 0.f, 0.f);
            if (ge < E) { int sn = src[ge]; v = nfg[(size_t)sn * 8 + c]; }
            float* xr = s_x + e * X_STRIDE + c * 4;
            xr[0] = v.x; xr[1] = v.y; xr[2] = v.z; xr[3] = v.w;
        }
    }
    __syncthreads();

    // -------- phase A: h = relu(ef@W1+b1) -> s_h fp32 [128][132] --------
    {
        int e = t >> 1, half = t & 1;
        float er[EDIM];
#pragma unroll
        for (int d = 0; d < EDIM; d++) er[d] = s_ef[e * EDIM + d];
        int j0 = half * 64;
#pragma unroll
        for (int jj = 0; jj < 64; jj += 4) {
            int j = j0 + jj;
            float4 acc = *(const float4*)(s_b1 + j);
#pragma unroll
            for (int d = 0; d < EDIM; d++) {
                float4 w = *(const float4*)(s_w1 + d * EH + j);
                acc.x += er[d] * w.x; acc.y += er[d] * w.y;
                acc.z += er[d] * w.z; acc.w += er[d] * w.w;
            }
            s_h[e * H_STRIDE + j + 0] = fmaxf(acc.x, 0.f);
            s_h[e * H_STRIDE + j + 1] = fmaxf(acc.y, 0.f);
            s_h[e * H_STRIDE + j + 2] = fmaxf(acc.z, 0.f);
            s_h[e * H_STRIDE + j + 3] = fmaxf(acc.w, 0.f);
        }
    }
    __syncthreads();

    // -------- load A fragments (hi/lo) into registers --------
    const int g  = lane >> 2;
    const int c4 = lane & 3;
    const int er0 = wid * 16 + g;      // edge row for d0/d1
    const int er1 = er0 + 8;           // edge row for d2/d3
    uint32_t ahi[8][4], alo[8][4];
#pragma unroll
    for (int ks = 0; ks < 8; ks++) {
        int kb = ks * 16 + 2 * c4;
        float2 p0 = *(const float2*)(s_h + er0 * H_STRIDE + kb);
        float2 p1 = *(const float2*)(s_h + er1 * H_STRIDE + kb);
        float2 p2 = *(const float2*)(s_h + er0 * H_STRIDE + kb + 8);
        float2 p3 = *(const float2*)(s_h + er1 * H_STRIDE + kb + 8);
        split2(p0.x, p0.y, ahi[ks][0], alo[ks][0]);
        split2(p1.x, p1.y, ahi[ks][1], alo[ks][1]);
        split2(p2.x, p2.y, ahi[ks][2], alo[ks][2]);
        split2(p3.x, p3.y, ahi[ks][3], alo[ks][3]);
    }
    __syncthreads();   // all A frags read before s_h region is reused for B

    // -------- mainloop: sweep 128 n-tiles in 16 chunks, cp.async double-buffer --------
    auto stage = [&](int chunk) {
        const uint4* srcp = g_Bfrag + chunk * 2048;
        uint32_t dstbase = sbase + ((chunk & 1) ? OFF_BB1 : OFF_BB0);
#pragma unroll
        for (int j = t; j < 2048; j += NTH) {
            uint32_t d = dstbase + j * 16;
            size_t gp = (size_t)__cvta_generic_to_global(srcp + j);
            asm volatile("cp.async.cg.shared.global [%0], [%1], 16;"
                         :: "r"(d), "l"(gp) : "memory");
        }
        asm volatile("cp.async.commit_group;" ::: "memory");
    };

    stage(0);
    stage(1);

    float acc[16];
#pragma unroll
    for (int i = 0; i < 16; i++) acc[i] = 0.f;

    for (int ch = 0; ch < 16; ch++) {
        asm volatile("cp.async.wait_group 1;" ::: "memory");
        __syncthreads();
        const uint4* bb = (const uint4*)(sm + ((ch & 1) ? OFF_BB1 : OFF_BB0));
#pragma unroll
        for (int ntl = 0; ntl < 8; ntl++) {
            int nt = ch * 8 + ntl;
            float d0 = 0.f, d1 = 0.f, d2 = 0.f, d3 = 0.f;
            const uint4* bp = bb + ntl * 256 + lane;
#pragma unroll
            for (int ks = 0; ks < 8; ks++) {
                uint4 b = bp[ks * 32];
                mma_bf16(d0, d1, d2, d3, ahi[ks][0], ahi[ks][1], ahi[ks][2], ahi[ks][3], b.x, b.y);
                mma_bf16(d0, d1, d2, d3, alo[ks][0], alo[ks][1], alo[ks][2], alo[ks][3], b.x, b.y);
                mma_bf16(d0, d1, d2, d3, ahi[ks][0], ahi[ks][1], ahi[ks][2], ahi[ks][3], b.z, b.w);
            }
            int i  = nt >> 2;
            int t4 = nt & 3;
            float xi0 = s_x[er0 * X_STRIDE + i];
            float xi1 = s_x[er1 * X_STRIDE + i];
            acc[t4 * 2 + 0]     = fmaf(xi0, d0, acc[t4 * 2 + 0]);
            acc[t4 * 2 + 1]     = fmaf(xi0, d1, acc[t4 * 2 + 1]);
            acc[8 + t4 * 2 + 0] = fmaf(xi1, d2, acc[8 + t4 * 2 + 0]);
            acc[8 + t4 * 2 + 1] = fmaf(xi1, d3, acc[8 + t4 * 2 + 1]);
        }
        __syncthreads();
        if (ch + 2 < 16) stage(ch + 2);
    }

    // -------- b2 term: msg[e,o] += sum_i x[e,i] * b2[i*32+o] --------
    const int ob = 2 * c4;
#pragma unroll 8
    for (int i = 0; i < HID; i++) {
        float xi0 = s_x[er0 * X_STRIDE + i];
        float xi1 = s_x[er1 * X_STRIDE + i];
#pragma unroll
        for (int t4 = 0; t4 < 4; t4++) {
            float2 bv = *(const float2*)(s_b2 + i * HID + t4 * 8 + ob);
            acc[t4 * 2 + 0]     = fmaf(xi0, bv.x, acc[t4 * 2 + 0]);
            acc[t4 * 2 + 1]     = fmaf(xi0, bv.y, acc[t4 * 2 + 1]);
            acc[8 + t4 * 2 + 0] = fmaf(xi1, bv.x, acc[8 + t4 * 2 + 0]);
            acc[8 + t4 * 2 + 1] = fmaf(xi1, bv.y, acc[8 + t4 * 2 + 1]);
        }
    }

    // -------- scatter-add --------
    {
        int ge0 = e0g + er0;
        if (ge0 < E) {
            int dn = dst[ge0];
            float* op = out + (size_t)dn * HID;
#pragma unroll
            for (int t4 = 0; t4 < 4; t4++) {
                atomicAdd(op + t4 * 8 + ob + 0, acc[t4 * 2 + 0]);
                atomicAdd(op + t4 * 8 + ob + 1, acc[t4 * 2 + 1]);
            }
        }
        int ge1 = e0g + er1;
        if (ge1 < E) {
            int dn = dst[ge1];
            float* op = out + (size_t)dn * HID;
#pragma unroll
            for (int t4 = 0; t4 < 4; t4++) {
                atomicAdd(op + t4 * 8 + ob + 0, acc[8 + t4 * 2 + 0]);
                atomicAdd(op + t4 * 8 + ob + 1, acc[8 + t4 * 2 + 1]);
            }
        }
    }
}

extern "C" void kernel_launch(void* const* d_in, const int* in_sizes, int n_in,
                              void* d_out, int out_size) {
    const float* nf   = (const float*)d_in[0];
    const float* ef   = (const float*)d_in[1];
    const int*   src  = (const int*)d_in[2];
    const int*   dst  = (const int*)d_in[3];
    const float* W1   = (const float*)d_in[4];
    const float* b1   = (const float*)d_in[5];
    const float* W2   = (const float*)d_in[6];
    const float* b2   = (const float*)d_in[7];
    const float* bias = (const float*)d_in[8];
    float* out = (float*)d_out;

    const int E = in_sizes[2];

    cudaFuncSetAttribute(mpnn_mma_kernel,
                         cudaFuncAttributeMaxDynamicSharedMemorySize, SMEM_TOTAL);

    prep_b_kernel<<<128, 256>>>(W2);
    init_out_kernel<<<(out_size + 255) / 256, 256>>>(out, bias, out_size);

    int grid = (E + TE - 1) / TE;
    mpnn_mma_kernel<<<grid, NTH, SMEM_TOTAL>>>(nf, ef, src, dst, W1, b1, b2, out, E);
}

// round 6
// speedup vs baseline: 3.4669x; 1.0384x over previous
#include <cuda_runtime.h>
#include <cuda_bf16.h>
#include <cstdint>

#define HID   32
#define EDIM  16
#define EH    128
#define TE    256
#define NTH   256
#define H_STRIDE 132
#define X_STRIDE 33

// ---- smem offsets (bytes) ----
#define OFF_X    0            // 256 x 33 f32 = 33792
#define OFF_B2   33792        // 4096 -> end 37888
#define OFF_BB0  38912        // 32768 B buffer 0 (overlays s_h after frag load)
#define OFF_BB1  71680        // 32768 B buffer 1
#define OFF_H    38912        // s_h fp32 [256][132] = 135168 -> end 174080 (transient)
#define OFF_EF   174080       // 256*16*4 = 16384
#define OFF_W1   190464       // 8192
#define OFF_B1   198656       // 512
#define SMEM_TOTAL 199680

// W2 pre-split into mma.sync fragment order: [nt(128)][ks(8)][lane(32)] = {hi01,hi23,lo01,lo23}
__device__ uint4 g_Bfrag[128 * 8 * 32];

__device__ __forceinline__ uint32_t smem_u32(const void* p) {
    uint32_t a;
    asm("{ .reg .u64 t; cvta.to.shared.u64 t, %1; cvt.u32.u64 %0, t; }" : "=r"(a) : "l"(p));
    return a;
}
__device__ __forceinline__ uint32_t pkh(__nv_bfloat16 a, __nv_bfloat16 b) {
    __nv_bfloat162 v = __halves2bfloat162(a, b);
    return *reinterpret_cast<uint32_t*>(&v);
}
__device__ __forceinline__ void split2(float a, float b, uint32_t& hi, uint32_t& lo) {
    __nv_bfloat16 ha = __float2bfloat16(a), hb = __float2bfloat16(b);
    float ra = a - __bfloat162float(ha);
    float rb = b - __bfloat162float(hb);
    hi = pkh(ha, hb);
    lo = pkh(__float2bfloat16(ra), __float2bfloat16(rb));
}
__device__ __forceinline__ void mma_bf16(float& d0, float& d1, float& d2, float& d3,
                                         uint32_t a0, uint32_t a1, uint32_t a2, uint32_t a3,
                                         uint32_t b0, uint32_t b1) {
    asm volatile(
        "mma.sync.aligned.m16n8k16.row.col.f32.bf16.bf16.f32 "
        "{%0,%1,%2,%3}, {%4,%5,%6,%7}, {%8,%9}, {%0,%1,%2,%3};"
        : "+f"(d0), "+f"(d1), "+f"(d2), "+f"(d3)
        : "r"(a0), "r"(a1), "r"(a2), "r"(a3), "r"(b0), "r"(b1));
}

// ---------------- prep: W2 -> fragment-ordered bf16 hi/lo ----------------
__global__ void prep_b_kernel(const float* __restrict__ W2) {
    int idx = blockIdx.x * blockDim.x + threadIdx.x;
    if (idx >= 128 * 8 * 32) return;
    int lane = idx & 31, ks = (idx >> 5) & 7, nt = idx >> 8;
    int g = lane >> 2, c = lane & 3;
    int n = nt * 8 + g;
    int k0 = ks * 16 + 2 * c;
    float v0 = W2[(size_t)k0 * 1024 + n];
    float v1 = W2[(size_t)(k0 + 1) * 1024 + n];
    float v2 = W2[(size_t)(k0 + 8) * 1024 + n];
    float v3 = W2[(size_t)(k0 + 9) * 1024 + n];
    uint4 r;
    split2(v0, v1, r.x, r.z);
    split2(v2, v3, r.y, r.w);
    g_Bfrag[idx] = r;
}

__global__ void init_out_kernel(float* __restrict__ out,
                                const float* __restrict__ bias, int n) {
    int i = blockIdx.x * blockDim.x + threadIdx.x;
    if (i < n) out[i] = bias[i & (HID - 1)];
}

// ---------------- main fused kernel ----------------
__global__ __launch_bounds__(NTH, 1)
void mpnn_mma_kernel(const float* __restrict__ nf,
                     const float* __restrict__ ef,
                     const int*   __restrict__ src,
                     const int*   __restrict__ dst,
                     const float* __restrict__ W1,
                     const float* __restrict__ b1,
                     const float* __restrict__ b2,
                     float* __restrict__ out,
                     int E) {
    extern __shared__ __align__(1024) char sm[];
    const uint32_t sbase = smem_u32(sm);
    const int t = threadIdx.x;
    const int wid = t >> 5;
    const int lane = t & 31;
    const int e0g = blockIdx.x * TE;

    float* s_x  = (float*)(sm + OFF_X);
    float* s_b2 = (float*)(sm + OFF_B2);
    float* s_ef = (float*)(sm + OFF_EF);
    float* s_w1 = (float*)(sm + OFF_W1);
    float* s_b1 = (float*)(sm + OFF_B1);
    float* s_h  = (float*)(sm + OFF_H);

    // -------- phase 0: cooperative loads --------
    {
        const float4* efg = (const float4*)ef;
        float4* efs = (float4*)s_ef;
        for (int i = t; i < TE * EDIM / 4; i += NTH) {
            int ge = e0g + (i >> 2);
            float4 v = make_float4(0.f, 0.f, 0.f, 0.f);
            if (ge < E) v = efg[(size_t)e0g * 4 + i];
            efs[i] = v;
        }
        const float4* w1g = (const float4*)W1;
        float4* w1s = (float4*)s_w1;
        for (int i = t; i < EDIM * EH / 4; i += NTH) w1s[i] = w1g[i];
        if (t < EH / 4) ((float4*)s_b1)[t] = ((const float4*)b1)[t];
        for (int i = t; i < HID * HID / 4; i += NTH)
            ((float4*)s_b2)[i] = ((const float4*)b2)[i];
        const float4* nfg = (const float4*)nf;
        for (int j = t; j < TE * 8; j += NTH) {
            int e = j >> 3, c = j & 7, ge = e0g + e;
            float4 v = make_float4(0.f, 0.f, 0.f, 0.f);
            if (ge < E) { int sn = src[ge]; v = nfg[(size_t)sn * 8 + c]; }
            float* xr = s_x + e * X_STRIDE + c * 4;
            xr[0] = v.x; xr[1] = v.y; xr[2] = v.z; xr[3] = v.w;
        }
    }
    __syncthreads();

    // -------- phase A: h = relu(ef@W1+b1) -> s_h fp32 [256][132] --------
    {
        int e = t;   // one edge per thread
        float er[EDIM];
#pragma unroll
        for (int d = 0; d < EDIM; d++) er[d] = s_ef[e * EDIM + d];
#pragma unroll 4
        for (int j = 0; j < EH; j += 4) {
            float4 acc = *(const float4*)(s_b1 + j);
#pragma unroll
            for (int d = 0; d < EDIM; d++) {
                float4 w = *(const float4*)(s_w1 + d * EH + j);
                acc.x += er[d] * w.x; acc.y += er[d] * w.y;
                acc.z += er[d] * w.z; acc.w += er[d] * w.w;
            }
            s_h[e * H_STRIDE + j + 0] = fmaxf(acc.x, 0.f);
            s_h[e * H_STRIDE + j + 1] = fmaxf(acc.y, 0.f);
            s_h[e * H_STRIDE + j + 2] = fmaxf(acc.z, 0.f);
            s_h[e * H_STRIDE + j + 3] = fmaxf(acc.w, 0.f);
        }
    }
    __syncthreads();

    // -------- load A fragments (hi/lo) for 2 m-tiles into registers --------
    const int g  = lane >> 2;
    const int c4 = lane & 3;
    const int eb = wid * 32;
    const int er0 = eb + g,      er1 = er0 + 8;   // m-tile 0
    const int er2 = eb + 16 + g, er3 = er2 + 8;   // m-tile 1
    uint32_t ahi0[8][4], alo0[8][4], ahi1[8][4], alo1[8][4];
#pragma unroll
    for (int ks = 0; ks < 8; ks++) {
        int kb = ks * 16 + 2 * c4;
        float2 p;
        p = *(const float2*)(s_h + er0 * H_STRIDE + kb);     split2(p.x, p.y, ahi0[ks][0], alo0[ks][0]);
        p = *(const float2*)(s_h + er1 * H_STRIDE + kb);     split2(p.x, p.y, ahi0[ks][1], alo0[ks][1]);
        p = *(const float2*)(s_h + er0 * H_STRIDE + kb + 8); split2(p.x, p.y, ahi0[ks][2], alo0[ks][2]);
        p = *(const float2*)(s_h + er1 * H_STRIDE + kb + 8); split2(p.x, p.y, ahi0[ks][3], alo0[ks][3]);
        p = *(const float2*)(s_h + er2 * H_STRIDE + kb);     split2(p.x, p.y, ahi1[ks][0], alo1[ks][0]);
        p = *(const float2*)(s_h + er3 * H_STRIDE + kb);     split2(p.x, p.y, ahi1[ks][1], alo1[ks][1]);
        p = *(const float2*)(s_h + er2 * H_STRIDE + kb + 8); split2(p.x, p.y, ahi1[ks][2], alo1[ks][2]);
        p = *(const float2*)(s_h + er3 * H_STRIDE + kb + 8); split2(p.x, p.y, ahi1[ks][3], alo1[ks][3]);
    }
    __syncthreads();   // all A frags read before s_h region is reused for B

    // -------- mainloop: 128 n-tiles in 16 chunks, cp.async double-buffer --------
    auto stage = [&](int chunk) {
        const uint4* srcp = g_Bfrag + chunk * 2048;
        uint32_t dstbase = sbase + ((chunk & 1) ? OFF_BB1 : OFF_BB0);
#pragma unroll
        for (int j = t; j < 2048; j += NTH) {
            uint32_t d = dstbase + j * 16;
            size_t gp = (size_t)__cvta_generic_to_global(srcp + j);
            asm volatile("cp.async.cg.shared.global [%0], [%1], 16;"
                         :: "r"(d), "l"(gp) : "memory");
        }
        asm volatile("cp.async.commit_group;" ::: "memory");
    };

    stage(0);
    stage(1);

    float acc[32];
#pragma unroll
    for (int i = 0; i < 32; i++) acc[i] = 0.f;

    for (int ch = 0; ch < 16; ch++) {
        asm volatile("cp.async.wait_group 1;" ::: "memory");
        __syncthreads();
        const uint4* bb = (const uint4*)(sm + ((ch & 1) ? OFF_BB1 : OFF_BB0));
#pragma unroll
        for (int ntl = 0; ntl < 8; ntl++) {
            int nt = ch * 8 + ntl;
            float d0 = 0.f, d1 = 0.f, d2 = 0.f, d3 = 0.f;
            float e0 = 0.f, e1 = 0.f, e2 = 0.f, e3 = 0.f;
            const uint4* bp = bb + ntl * 256 + lane;
#pragma unroll
            for (int ks = 0; ks < 8; ks++) {
                uint4 b = bp[ks * 32];
                mma_bf16(d0, d1, d2, d3, ahi0[ks][0], ahi0[ks][1], ahi0[ks][2], ahi0[ks][3], b.x, b.y);
                mma_bf16(d0, d1, d2, d3, alo0[ks][0], alo0[ks][1], alo0[ks][2], alo0[ks][3], b.x, b.y);
                mma_bf16(d0, d1, d2, d3, ahi0[ks][0], ahi0[ks][1], ahi0[ks][2], ahi0[ks][3], b.z, b.w);
                mma_bf16(e0, e1, e2, e3, ahi1[ks][0], ahi1[ks][1], ahi1[ks][2], ahi1[ks][3], b.x, b.y);
                mma_bf16(e0, e1, e2, e3, alo1[ks][0], alo1[ks][1], alo1[ks][2], alo1[ks][3], b.x, b.y);
                mma_bf16(e0, e1, e2, e3, ahi1[ks][0], ahi1[ks][1], ahi1[ks][2], ahi1[ks][3], b.z, b.w);
            }
            int i  = nt >> 2;
            int t4 = nt & 3;
            float xi0 = s_x[er0 * X_STRIDE + i];
            float xi1 = s_x[er1 * X_STRIDE + i];
            float xi2 = s_x[er2 * X_STRIDE + i];
            float xi3 = s_x[er3 * X_STRIDE + i];
            acc[t4 * 2 + 0]      = fmaf(xi0, d0, acc[t4 * 2 + 0]);
            acc[t4 * 2 + 1]      = fmaf(xi0, d1, acc[t4 * 2 + 1]);
            acc[8 + t4 * 2 + 0]  = fmaf(xi1, d2, acc[8 + t4 * 2 + 0]);
            acc[8 + t4 * 2 + 1]  = fmaf(xi1, d3, acc[8 + t4 * 2 + 1]);
            acc[16 + t4 * 2 + 0] = fmaf(xi2, e0, acc[16 + t4 * 2 + 0]);
            acc[16 + t4 * 2 + 1] = fmaf(xi2, e1, acc[16 + t4 * 2 + 1]);
            acc[24 + t4 * 2 + 0] = fmaf(xi3, e2, acc[24 + t4 * 2 + 0]);
            acc[24 + t4 * 2 + 1] = fmaf(xi3, e3, acc[24 + t4 * 2 + 1]);
        }
        __syncthreads();
        if (ch + 2 < 16) stage(ch + 2);
    }

    // -------- b2 term: msg[e,o] += sum_i x[e,i] * b2[i*32+o] --------
    const int ob = 2 * c4;
#pragma unroll 8
    for (int i = 0; i < HID; i++) {
        float xi0 = s_x[er0 * X_STRIDE + i];
        float xi1 = s_x[er1 * X_STRIDE + i];
        float xi2 = s_x[er2 * X_STRIDE + i];
        float xi3 = s_x[er3 * X_STRIDE + i];
#pragma unroll
        for (int t4 = 0; t4 < 4; t4++) {
            float2 bv = *(const float2*)(s_b2 + i * HID + t4 * 8 + ob);
            acc[t4 * 2 + 0]      = fmaf(xi0, bv.x, acc[t4 * 2 + 0]);
            acc[t4 * 2 + 1]      = fmaf(xi0, bv.y, acc[t4 * 2 + 1]);
            acc[8 + t4 * 2 + 0]  = fmaf(xi1, bv.x, acc[8 + t4 * 2 + 0]);
            acc[8 + t4 * 2 + 1]  = fmaf(xi1, bv.y, acc[8 + t4 * 2 + 1]);
            acc[16 + t4 * 2 + 0] = fmaf(xi2, bv.x, acc[16 + t4 * 2 + 0]);
            acc[16 + t4 * 2 + 1] = fmaf(xi2, bv.y, acc[16 + t4 * 2 + 1]);
            acc[24 + t4 * 2 + 0] = fmaf(xi3, bv.x, acc[24 + t4 * 2 + 0]);
            acc[24 + t4 * 2 + 1] = fmaf(xi3, bv.y, acc[24 + t4 * 2 + 1]);
        }
    }

    // -------- scatter-add --------
    {
        const int ers[4] = {er0, er1, er2, er3};
#pragma unroll
        for (int r = 0; r < 4; r++) {
            int ge = e0g + ers[r];
            if (ge < E) {
                int dn = dst[ge];
                float* op = out + (size_t)dn * HID;
#pragma unroll
                for (int t4 = 0; t4 < 4; t4++) {
                    atomicAdd(op + t4 * 8 + ob + 0, acc[r * 8 + t4 * 2 + 0]);
                    atomicAdd(op + t4 * 8 + ob + 1, acc[r * 8 + t4 * 2 + 1]);
                }
            }
        }
    }
}

extern "C" void kernel_launch(void* const* d_in, const int* in_sizes, int n_in,
                              void* d_out, int out_size) {
    const float* nf   = (const float*)d_in[0];
    const float* ef   = (const float*)d_in[1];
    const int*   src  = (const int*)d_in[2];
    const int*   dst  = (const int*)d_in[3];
    const float* W1   = (const float*)d_in[4];
    const float* b1   = (const float*)d_in[5];
    const float* W2   = (const float*)d_in[6];
    const float* b2   = (const float*)d_in[7];
    const float* bias = (const float*)d_in[8];
    float* out = (float*)d_out;

    const int E = in_sizes[2];

    cudaFuncSetAttribute(mpnn_mma_kernel,
                         cudaFuncAttributeMaxDynamicSharedMemorySize, SMEM_TOTAL);

    prep_b_kernel<<<128, 256>>>(W2);
    init_out_kernel<<<(out_size + 255) / 256, 256>>>(out, bias, out_size);

    int grid = (E + TE - 1) / TE;
    mpnn_mma_kernel<<<grid, NTH, SMEM_TOTAL>>>(nf, ef, src, dst, W1, b1, b2, out, E);
}